// round 2
// baseline (speedup 1.0000x reference)
#include <cuda_runtime.h>
#include <cuda_bf16.h>
#include <cstdint>

#define WSZ 7
#define NHD 8
#define HDIM 32
#define CDIM 256
#define HW 224
#define BATCH 4
#define NTOK (HW*HW)          // 50176
#define MTOT (BATCH*NTOK)     // 200704
#define N3 768                // 3*C

// ---------------- scratch (static device allocations only) ----------------
__device__ __nv_bfloat16 g_xhi[(size_t)MTOT*CDIM];
__device__ __nv_bfloat16 g_xlo[(size_t)MTOT*CDIM];
__device__ __nv_bfloat16 g_whi[N3*CDIM];
__device__ __nv_bfloat16 g_wlo[N3*CDIM];
__device__ float g_qkv[(size_t)MTOT*N3];
__device__ float g_bias[NHD*49*49];

// ---------------- split fp32 -> bf16 hi/lo ----------------
__global__ void split_x_kernel(const float2* __restrict__ x, int n2) {
    int i = blockIdx.x * blockDim.x + threadIdx.x;
    if (i >= n2) return;
    float2 v = x[i];
    __nv_bfloat16 h0 = __float2bfloat16(v.x);
    __nv_bfloat16 h1 = __float2bfloat16(v.y);
    __nv_bfloat16 l0 = __float2bfloat16(v.x - __bfloat162float(h0));
    __nv_bfloat16 l1 = __float2bfloat16(v.y - __bfloat162float(h1));
    reinterpret_cast<__nv_bfloat162*>(g_xhi)[i] = __halves2bfloat162(h0, h1);
    reinterpret_cast<__nv_bfloat162*>(g_xlo)[i] = __halves2bfloat162(l0, l1);
}

__global__ void split_w_kernel(const float2* __restrict__ w, int n2) {
    int i = blockIdx.x * blockDim.x + threadIdx.x;
    if (i >= n2) return;
    float2 v = w[i];
    __nv_bfloat16 h0 = __float2bfloat16(v.x);
    __nv_bfloat16 h1 = __float2bfloat16(v.y);
    __nv_bfloat16 l0 = __float2bfloat16(v.x - __bfloat162float(h0));
    __nv_bfloat16 l1 = __float2bfloat16(v.y - __bfloat162float(h1));
    reinterpret_cast<__nv_bfloat162*>(g_whi)[i] = __halves2bfloat162(h0, h1);
    reinterpret_cast<__nv_bfloat162*>(g_wlo)[i] = __halves2bfloat162(l0, l1);
}

// ---------------- relative-position bias gather ----------------
__global__ void build_bias_kernel(const float* __restrict__ table) {
    int t = blockIdx.x * blockDim.x + threadIdx.x;
    if (t >= NHD * 49 * 49) return;
    int h = t / 2401;
    int r = t % 2401;
    int q = r / 49, k = r % 49;
    int qi = q / 7, qj = q % 7, ki = k / 7, kj = k % 7;
    int rel = (qi - ki + 6) * 13 + (qj - kj + 6);
    g_bias[t] = table[rel * NHD + h];
}

// ---------------- QKV GEMM: split-bf16, mma.sync m16n8k16 ----------------
// out[m, n] = sum_k x[m,k]*w[n,k] + b[n]
// 3 segments: (x_hi,w_hi), (x_lo,w_hi), (x_hi,w_lo)
// CTA tile 128(M) x 64(N), K-tile 32, 256 threads = 8 warps (4m x 2n), warp 32x32.
__global__ __launch_bounds__(256, 2) void qkv_gemm_kernel(const float* __restrict__ qkv_b) {
    __shared__ __nv_bfloat16 As[128 * 34];
    __shared__ __nv_bfloat16 Bs[64 * 34];

    const int tid = threadIdx.x;
    const int lane = tid & 31;
    const int w = tid >> 5;
    const int wm = (w & 3) * 32;
    const int wn = (w >> 2) * 32;
    const int g = lane >> 2;      // groupID
    const int tg = lane & 3;      // thread in group
    const int mbase = blockIdx.y * 128;
    const int nbase = blockIdx.x * 64;

    float acc[2][4][4];
#pragma unroll
    for (int mi = 0; mi < 2; ++mi)
#pragma unroll
        for (int ni = 0; ni < 4; ++ni)
#pragma unroll
            for (int e = 0; e < 4; ++e) acc[mi][ni][e] = 0.f;

    for (int ks = 0; ks < 24; ++ks) {
        const int seg = ks >> 3;
        const int k0 = (ks & 7) << 5;
        const __nv_bfloat16* Ag = (seg == 1) ? g_xlo : g_xhi;
        const __nv_bfloat16* Bg = (seg == 2) ? g_wlo : g_whi;

#pragma unroll
        for (int j = 0; j < 8; ++j) {
            int i = tid + j * 256;
            int r = i >> 4, cu = (i & 15) << 1;
            *reinterpret_cast<uint32_t*>(&As[r * 34 + cu]) =
                *reinterpret_cast<const uint32_t*>(Ag + (size_t)(mbase + r) * CDIM + k0 + cu);
        }
#pragma unroll
        for (int j = 0; j < 4; ++j) {
            int i = tid + j * 256;
            int r = i >> 4, cu = (i & 15) << 1;
            *reinterpret_cast<uint32_t*>(&Bs[r * 34 + cu]) =
                *reinterpret_cast<const uint32_t*>(Bg + (size_t)(nbase + r) * CDIM + k0 + cu);
        }
        __syncthreads();

#pragma unroll
        for (int kk = 0; kk < 32; kk += 16) {
            uint32_t afr[2][4], bfr[4][2];
#pragma unroll
            for (int mi = 0; mi < 2; ++mi) {
                int rm = wm + mi * 16;
                afr[mi][0] = *reinterpret_cast<uint32_t*>(&As[(rm + g) * 34 + kk + tg * 2]);
                afr[mi][1] = *reinterpret_cast<uint32_t*>(&As[(rm + g + 8) * 34 + kk + tg * 2]);
                afr[mi][2] = *reinterpret_cast<uint32_t*>(&As[(rm + g) * 34 + kk + tg * 2 + 8]);
                afr[mi][3] = *reinterpret_cast<uint32_t*>(&As[(rm + g + 8) * 34 + kk + tg * 2 + 8]);
            }
#pragma unroll
            for (int ni = 0; ni < 4; ++ni) {
                int rn = wn + ni * 8 + g;
                bfr[ni][0] = *reinterpret_cast<uint32_t*>(&Bs[rn * 34 + kk + tg * 2]);
                bfr[ni][1] = *reinterpret_cast<uint32_t*>(&Bs[rn * 34 + kk + tg * 2 + 8]);
            }
#pragma unroll
            for (int mi = 0; mi < 2; ++mi)
#pragma unroll
                for (int ni = 0; ni < 4; ++ni) {
                    asm volatile(
                        "mma.sync.aligned.m16n8k16.row.col.f32.bf16.bf16.f32 "
                        "{%0,%1,%2,%3}, {%4,%5,%6,%7}, {%8,%9}, {%0,%1,%2,%3};\n"
                        : "+f"(acc[mi][ni][0]), "+f"(acc[mi][ni][1]),
                          "+f"(acc[mi][ni][2]), "+f"(acc[mi][ni][3])
                        : "r"(afr[mi][0]), "r"(afr[mi][1]), "r"(afr[mi][2]), "r"(afr[mi][3]),
                          "r"(bfr[ni][0]), "r"(bfr[ni][1]));
                }
        }
        __syncthreads();
    }

#pragma unroll
    for (int mi = 0; mi < 2; ++mi)
#pragma unroll
        for (int ni = 0; ni < 4; ++ni) {
            int mg0 = mbase + wm + mi * 16 + g;
            int n0 = nbase + wn + ni * 8 + tg * 2;
            float b0 = qkv_b[n0], b1 = qkv_b[n0 + 1];
            float2 v0 = make_float2(acc[mi][ni][0] + b0, acc[mi][ni][1] + b1);
            float2 v1 = make_float2(acc[mi][ni][2] + b0, acc[mi][ni][3] + b1);
            *reinterpret_cast<float2*>(&g_qkv[(size_t)mg0 * N3 + n0]) = v0;
            *reinterpret_cast<float2*>(&g_qkv[(size_t)(mg0 + 8) * N3 + n0]) = v1;
        }
}

// ---------------- windowed attention ----------------
// One CTA per (window, head). 49 tokens padded to 52. Shift folded into gather;
// output scatter target equals gather source (roll(+s) inverts roll(-s)).
__global__ __launch_bounds__(128) void attn_kernel(const float* __restrict__ mask,
                                                   float* __restrict__ out) {
    __shared__ float qs[52][33];
    __shared__ float kk_[52][33];
    __shared__ float vs[52][33];
    __shared__ float S[52][53];

    const int tid = threadIdx.x;
    const int bid = blockIdx.x;
    const int head = bid & 7;
    const int win = bid >> 3;
    const int b = win >> 10;
    const int widx = win & 1023;
    const int wy = widx >> 5, wx = widx & 31;

    for (int idx = tid; idx < 52 * 32; idx += 128) {
        int p = idx >> 5, d = idx & 31;
        float qv = 0.f, kv = 0.f, vv = 0.f;
        if (p < 49) {
            int i = p / 7, j = p % 7;
            int sh = wy * 7 + i + 3; if (sh >= HW) sh -= HW;
            int sw = wx * 7 + j + 3; if (sw >= HW) sw -= HW;
            size_t row = (size_t)b * NTOK + sh * HW + sw;
            const float* base = g_qkv + row * N3 + head * HDIM + d;
            qv = base[0]; kv = base[256]; vv = base[512];
        }
        qs[p][d] = qv; kk_[p][d] = kv; vs[p][d] = vv;
    }
    __syncthreads();

    const float scale = 0.17677669529663687f;  // 32^-0.5

    // S = QK^T * scale + bias + mask, 4x4 register blocks over (qi, ki)
    for (int blk = tid; blk < 169; blk += 128) {
        int bq = (blk / 13) * 4, bk = (blk % 13) * 4;
        float a[4][4] = {};
        for (int d = 0; d < 32; ++d) {
            float qr[4], kr[4];
#pragma unroll
            for (int r = 0; r < 4; ++r) qr[r] = qs[bq + r][d];
#pragma unroll
            for (int c = 0; c < 4; ++c) kr[c] = kk_[bk + c][d];
#pragma unroll
            for (int r = 0; r < 4; ++r)
#pragma unroll
                for (int c = 0; c < 4; ++c) a[r][c] += qr[r] * kr[c];
        }
#pragma unroll
        for (int r = 0; r < 4; ++r)
#pragma unroll
            for (int c = 0; c < 4; ++c) {
                int qi = bq + r, ki = bk + c;
                float sv;
                if (qi < 49 && ki < 49)
                    sv = a[r][c] * scale + g_bias[head * 2401 + qi * 49 + ki]
                         + mask[(size_t)widx * 2401 + qi * 49 + ki];
                else if (qi < 49)
                    sv = -1e30f;
                else
                    sv = 0.f;
                S[qi][ki] = sv;
            }
    }
    __syncthreads();

    // softmax per query row
    if (tid < 49) {
        float m = -1e30f;
        for (int k2 = 0; k2 < 52; ++k2) m = fmaxf(m, S[tid][k2]);
        float s = 0.f;
        for (int k2 = 0; k2 < 52; ++k2) {
            float e = __expf(S[tid][k2] - m);
            S[tid][k2] = e;
            s += e;
        }
        float inv = 1.f / s;
        for (int k2 = 0; k2 < 52; ++k2) S[tid][k2] *= inv;
    }
    __syncthreads();

    // O = P @ V, 4x4 blocks over (qi, d); write back to gather-source coords
    for (int blk = tid; blk < 104; blk += 128) {
        int bq = (blk >> 3) * 4, bd = (blk & 7) * 4;
        float a[4][4] = {};
        for (int k2 = 0; k2 < 52; ++k2) {
            float pr[4], vr[4];
#pragma unroll
            for (int r = 0; r < 4; ++r) pr[r] = S[bq + r][k2];
#pragma unroll
            for (int c = 0; c < 4; ++c) vr[c] = vs[k2][bd + c];
#pragma unroll
            for (int r = 0; r < 4; ++r)
#pragma unroll
                for (int c = 0; c < 4; ++c) a[r][c] += pr[r] * vr[c];
        }
#pragma unroll
        for (int r = 0; r < 4; ++r) {
            int qi = bq + r;
            if (qi < 49) {
                int i = qi / 7, j = qi % 7;
                int sh = wy * 7 + i + 3; if (sh >= HW) sh -= HW;
                int sw = wx * 7 + j + 3; if (sw >= HW) sw -= HW;
                size_t row = (size_t)b * NTOK + sh * HW + sw;
                float4 o = make_float4(a[r][0], a[r][1], a[r][2], a[r][3]);
                *reinterpret_cast<float4*>(&out[row * CDIM + head * HDIM + bd]) = o;
            }
        }
    }
}

// ---------------- launch ----------------
extern "C" void kernel_launch(void* const* d_in, const int* in_sizes, int n_in,
                              void* d_out, int out_size) {
    const float* x     = (const float*)d_in[0];
    const float* mask  = (const float*)d_in[1];
    const float* qkv_w = (const float*)d_in[2];
    const float* qkv_b = (const float*)d_in[3];
    const float* table = (const float*)d_in[4];
    float* out = (float*)d_out;

    int nx2 = MTOT * CDIM / 2;
    split_x_kernel<<<(nx2 + 255) / 256, 256>>>((const float2*)x, nx2);
    int nw2 = N3 * CDIM / 2;
    split_w_kernel<<<(nw2 + 255) / 256, 256>>>((const float2*)qkv_w, nw2);
    build_bias_kernel<<<(NHD * 2401 + 255) / 256, 256>>>(table);

    dim3 gg(N3 / 64, MTOT / 128);  // (12, 1568)
    qkv_gemm_kernel<<<gg, 256>>>(qkv_b);

    attn_kernel<<<BATCH * 1024 * NHD, 128>>>(mask, out);
}

// round 6
// speedup vs baseline: 1.2819x; 1.2819x over previous
#include <cuda_runtime.h>
#include <cuda_bf16.h>
#include <cstdint>

#define WSZ 7
#define NHD 8
#define HDIM 32
#define CDIM 256
#define HW 224
#define BATCH 4
#define NTOK (HW*HW)          // 50176
#define MTOT (BATCH*NTOK)     // 200704
#define N3 768                // 3*C
#define PAD 40                // smem row stride (bf16 elems): conflict-free for ldmatrix

// ---------------- scratch ----------------
__device__ __nv_bfloat16 g_whi[N3*CDIM];
__device__ __nv_bfloat16 g_wlo[N3*CDIM];
__device__ float g_qkv[(size_t)MTOT*N3];
__device__ float g_bias[NHD*49*49];

// ---------------- split w fp32 -> bf16 hi/lo ----------------
__global__ void split_w_kernel(const float2* __restrict__ w, int n2) {
    int i = blockIdx.x * blockDim.x + threadIdx.x;
    if (i >= n2) return;
    float2 v = w[i];
    __nv_bfloat16 h0 = __float2bfloat16(v.x);
    __nv_bfloat16 h1 = __float2bfloat16(v.y);
    __nv_bfloat16 l0 = __float2bfloat16(v.x - __bfloat162float(h0));
    __nv_bfloat16 l1 = __float2bfloat16(v.y - __bfloat162float(h1));
    reinterpret_cast<__nv_bfloat162*>(g_whi)[i] = __halves2bfloat162(h0, h1);
    reinterpret_cast<__nv_bfloat162*>(g_wlo)[i] = __halves2bfloat162(l0, l1);
}

// ---------------- relative-position bias gather ----------------
__global__ void build_bias_kernel(const float* __restrict__ table) {
    int t = blockIdx.x * blockDim.x + threadIdx.x;
    if (t >= NHD * 49 * 49) return;
    int h = t / 2401;
    int r = t % 2401;
    int q = r / 49, k = r % 49;
    int qi = q / 7, qj = q % 7, ki = k / 7, kj = k % 7;
    int rel = (qi - ki + 6) * 13 + (qj - kj + 6);
    g_bias[t] = table[rel * NHD + h];
}

// ---------------- helpers ----------------
__device__ __forceinline__ uint32_t s2u(const void* p) {
    return (uint32_t)__cvta_generic_to_shared(p);
}

#define LDSM4(R, ADDR)                                                          \
    asm volatile("ldmatrix.sync.aligned.m8n8.x4.shared.b16 {%0,%1,%2,%3}, [%4];" \
                 : "=r"((R)[0]), "=r"((R)[1]), "=r"((R)[2]), "=r"((R)[3])        \
                 : "r"(ADDR))

#define MMA16816(D, A, B0, B1)                                                   \
    asm volatile(                                                                \
        "mma.sync.aligned.m16n8k16.row.col.f32.bf16.bf16.f32 "                   \
        "{%0,%1,%2,%3}, {%4,%5,%6,%7}, {%8,%9}, {%0,%1,%2,%3};\n"                \
        : "+f"((D)[0]), "+f"((D)[1]), "+f"((D)[2]), "+f"((D)[3])                 \
        : "r"((A)[0]), "r"((A)[1]), "r"((A)[2]), "r"((A)[3]), "r"(B0), "r"(B1))

// ---------------- QKV GEMM: fused split-bf16, ldmatrix + mma ----------------
// out[m,n] = sum_k x[m,k] w[n,k] + b[n],   x fp32 split to hi/lo on the fly.
// CTA 128(M) x 128(N), k-tile 32, 256 thr = 8 warps, warp tile 64x32.
// Per k-tile, accumulate hi*whi + lo*whi + hi*wlo into one fp32 accumulator.
__global__ __launch_bounds__(256, 1) void qkv_gemm_kernel(
        const float* __restrict__ x, const float* __restrict__ qkv_b) {
    __shared__ __nv_bfloat16 Ahi[128 * PAD];
    __shared__ __nv_bfloat16 Alo[128 * PAD];
    __shared__ __nv_bfloat16 Bhi[128 * PAD];
    __shared__ __nv_bfloat16 Blo[128 * PAD];

    const int tid = threadIdx.x;
    const int lane = tid & 31;
    const int w = tid >> 5;
    const int wm = (w & 1) * 64;
    const int wn = (w >> 1) * 32;
    const int mbase = blockIdx.y * 128;
    const int nbase = blockIdx.x * 128;

    // ldmatrix lane addressing
    const int l8 = lane & 7;
    const int grp = lane >> 3;
    const int arow = l8 + (grp & 1) * 8;
    const int acol = (grp >> 1) * 8;

    // staging: thread -> (row, 16-elem half)
    const int sr = tid >> 1;
    const int sh = (tid & 1) * 16;
    const float* xbase = x + (size_t)(mbase + sr) * CDIM + sh;
    const __nv_bfloat16* whbase = g_whi + (size_t)(nbase + sr) * CDIM + sh;
    const __nv_bfloat16* wlbase = g_wlo + (size_t)(nbase + sr) * CDIM + sh;

    float acc[4][4][4];
#pragma unroll
    for (int mi = 0; mi < 4; ++mi)
#pragma unroll
        for (int nn = 0; nn < 4; ++nn)
#pragma unroll
            for (int e = 0; e < 4; ++e) acc[mi][nn][e] = 0.f;

    float4 a_st[4];
    uint4 bh_st[2], bl_st[2];

    // prologue: stage k-tile 0
    {
        const float* ap = xbase;
        a_st[0] = *(const float4*)(ap);
        a_st[1] = *(const float4*)(ap + 4);
        a_st[2] = *(const float4*)(ap + 8);
        a_st[3] = *(const float4*)(ap + 12);
        bh_st[0] = *(const uint4*)(whbase);
        bh_st[1] = *(const uint4*)(whbase + 8);
        bl_st[0] = *(const uint4*)(wlbase);
        bl_st[1] = *(const uint4*)(wlbase + 8);
    }

    for (int kt = 0; kt < 8; ++kt) {
        // convert + store staged tile to smem
        {
            __align__(16) __nv_bfloat16 hi[16];
            __align__(16) __nv_bfloat16 lo[16];
#pragma unroll
            for (int i = 0; i < 4; ++i) {
                float vv[4] = {a_st[i].x, a_st[i].y, a_st[i].z, a_st[i].w};
#pragma unroll
                for (int j = 0; j < 4; ++j) {
                    __nv_bfloat16 h = __float2bfloat16(vv[j]);
                    hi[i * 4 + j] = h;
                    lo[i * 4 + j] = __float2bfloat16(vv[j] - __bfloat162float(h));
                }
            }
            *(uint4*)&Ahi[sr * PAD + sh] = *(const uint4*)&hi[0];
            *(uint4*)&Ahi[sr * PAD + sh + 8] = *(const uint4*)&hi[8];
            *(uint4*)&Alo[sr * PAD + sh] = *(const uint4*)&lo[0];
            *(uint4*)&Alo[sr * PAD + sh + 8] = *(const uint4*)&lo[8];
            *(uint4*)&Bhi[sr * PAD + sh] = bh_st[0];
            *(uint4*)&Bhi[sr * PAD + sh + 8] = bh_st[1];
            *(uint4*)&Blo[sr * PAD + sh] = bl_st[0];
            *(uint4*)&Blo[sr * PAD + sh + 8] = bl_st[1];
        }
        __syncthreads();

        // prefetch next k-tile into registers
        if (kt < 7) {
            const float* ap = xbase + (kt + 1) * 32;
            a_st[0] = *(const float4*)(ap);
            a_st[1] = *(const float4*)(ap + 4);
            a_st[2] = *(const float4*)(ap + 8);
            a_st[3] = *(const float4*)(ap + 12);
            const __nv_bfloat16* bhp = whbase + (kt + 1) * 32;
            bh_st[0] = *(const uint4*)(bhp);
            bh_st[1] = *(const uint4*)(bhp + 8);
            const __nv_bfloat16* blp = wlbase + (kt + 1) * 32;
            bl_st[0] = *(const uint4*)(blp);
            bl_st[1] = *(const uint4*)(blp + 8);
        }

        // compute: 2 kk-steps of 16
#pragma unroll
        for (int kk = 0; kk < 32; kk += 16) {
            uint32_t ah[4][4], al[4][4], bh[4][2], bl[4][2];
#pragma unroll
            for (int mi = 0; mi < 4; ++mi) {
                int off = (wm + mi * 16 + arow) * PAD + kk + acol;
                LDSM4(ah[mi], s2u(&Ahi[off]));
                LDSM4(al[mi], s2u(&Alo[off]));
            }
#pragma unroll
            for (int nj = 0; nj < 2; ++nj) {
                int off = (wn + nj * 16 + arow) * PAD + kk + acol;
                uint32_t r[4];
                LDSM4(r, s2u(&Bhi[off]));
                bh[nj * 2][0] = r[0]; bh[nj * 2][1] = r[2];
                bh[nj * 2 + 1][0] = r[1]; bh[nj * 2 + 1][1] = r[3];
                LDSM4(r, s2u(&Blo[off]));
                bl[nj * 2][0] = r[0]; bl[nj * 2][1] = r[2];
                bl[nj * 2 + 1][0] = r[1]; bl[nj * 2 + 1][1] = r[3];
            }
#pragma unroll
            for (int mi = 0; mi < 4; ++mi)
#pragma unroll
                for (int nn = 0; nn < 4; ++nn) {
                    MMA16816(acc[mi][nn], ah[mi], bh[nn][0], bh[nn][1]);
                    MMA16816(acc[mi][nn], al[mi], bh[nn][0], bh[nn][1]);
                    MMA16816(acc[mi][nn], ah[mi], bl[nn][0], bl[nn][1]);
                }
        }
        __syncthreads();
    }

    // epilogue: add bias, store fp32
    const int g = lane >> 2;
    const int tg = lane & 3;
#pragma unroll
    for (int mi = 0; mi < 4; ++mi)
#pragma unroll
        for (int nn = 0; nn < 4; ++nn) {
            int m0 = mbase + wm + mi * 16 + g;
            int n0 = nbase + wn + nn * 8 + tg * 2;
            float b0 = qkv_b[n0], b1 = qkv_b[n0 + 1];
            float2 v0 = make_float2(acc[mi][nn][0] + b0, acc[mi][nn][1] + b1);
            float2 v1 = make_float2(acc[mi][nn][2] + b0, acc[mi][nn][3] + b1);
            *reinterpret_cast<float2*>(&g_qkv[(size_t)m0 * N3 + n0]) = v0;
            *reinterpret_cast<float2*>(&g_qkv[(size_t)(m0 + 8) * N3 + n0]) = v1;
        }
}

// ---------------- windowed attention (vectorized smem) ----------------
__global__ __launch_bounds__(128) void attn_kernel(const float* __restrict__ mask,
                                                   float* __restrict__ out) {
    __shared__ float qs[52][36];
    __shared__ float ks_[52][36];
    __shared__ float vs[52][36];
    __shared__ float S[52][56];

    const int tid = threadIdx.x;
    const int bid = blockIdx.x;
    const int head = bid & 7;
    const int win = bid >> 3;
    const int b = win >> 10;
    const int widx = win & 1023;
    const int wy = widx >> 5, wx = widx & 31;

    for (int idx = tid; idx < 52 * 8; idx += 128) {
        int p = idx >> 3, d4 = (idx & 7) << 2;
        float4 qv = make_float4(0.f, 0.f, 0.f, 0.f);
        float4 kv = qv, vv = qv;
        if (p < 49) {
            int i = p / 7, j = p % 7;
            int sh = wy * 7 + i + 3; if (sh >= HW) sh -= HW;
            int sw = wx * 7 + j + 3; if (sw >= HW) sw -= HW;
            size_t row = (size_t)b * NTOK + sh * HW + sw;
            const float* base = g_qkv + row * N3 + head * HDIM + d4;
            qv = *(const float4*)(base);
            kv = *(const float4*)(base + 256);
            vv = *(const float4*)(base + 512);
        }
        *(float4*)&qs[p][d4] = qv;
        *(float4*)&ks_[p][d4] = kv;
        *(float4*)&vs[p][d4] = vv;
    }
    __syncthreads();

    const float scale = 0.17677669529663687f;  // 32^-0.5

    // S = QK^T*scale + bias + mask, 4x4 blocks, float4 smem loads
    for (int blk = tid; blk < 169; blk += 128) {
        int bq = (blk / 13) * 4, bk = (blk % 13) * 4;
        float a[4][4] = {};
#pragma unroll
        for (int d = 0; d < 32; d += 4) {
            float4 qr[4], kr[4];
#pragma unroll
            for (int r = 0; r < 4; ++r) qr[r] = *(const float4*)&qs[bq + r][d];
#pragma unroll
            for (int c = 0; c < 4; ++c) kr[c] = *(const float4*)&ks_[bk + c][d];
#pragma unroll
            for (int r = 0; r < 4; ++r)
#pragma unroll
                for (int c = 0; c < 4; ++c)
                    a[r][c] += qr[r].x * kr[c].x + qr[r].y * kr[c].y
                             + qr[r].z * kr[c].z + qr[r].w * kr[c].w;
        }
#pragma unroll
        for (int r = 0; r < 4; ++r)
#pragma unroll
            for (int c = 0; c < 4; ++c) {
                int qi = bq + r, ki = bk + c;
                float sv;
                if (qi < 49 && ki < 49)
                    sv = a[r][c] * scale + g_bias[head * 2401 + qi * 49 + ki]
                         + mask[(size_t)widx * 2401 + qi * 49 + ki];
                else if (qi < 49)
                    sv = -1e30f;
                else
                    sv = 0.f;
                S[qi][ki] = sv;
            }
    }
    __syncthreads();

    // softmax per query row
    if (tid < 49) {
        float m = -1e30f;
        for (int k2 = 0; k2 < 52; ++k2) m = fmaxf(m, S[tid][k2]);
        float s = 0.f;
        for (int k2 = 0; k2 < 52; ++k2) {
            float e = __expf(S[tid][k2] - m);
            S[tid][k2] = e;
            s += e;
        }
        float inv = 1.f / s;
        for (int k2 = 0; k2 < 52; ++k2) S[tid][k2] *= inv;
    }
    __syncthreads();

    // O = P @ V, 4x4 blocks, float4 smem loads; scatter back to gather coords
    for (int blk = tid; blk < 104; blk += 128) {
        int bq = (blk >> 3) * 4, bd = (blk & 7) * 4;
        float a[4][4] = {};
#pragma unroll
        for (int k2 = 0; k2 < 52; k2 += 4) {
            float4 pr[4], vr[4];
#pragma unroll
            for (int r = 0; r < 4; ++r) pr[r] = *(const float4*)&S[bq + r][k2];
#pragma unroll
            for (int cc = 0; cc < 4; ++cc) vr[cc] = *(const float4*)&vs[k2 + cc][bd];
#pragma unroll
            for (int r = 0; r < 4; ++r) {
                a[r][0] += pr[r].x * vr[0].x + pr[r].y * vr[1].x + pr[r].z * vr[2].x + pr[r].w * vr[3].x;
                a[r][1] += pr[r].x * vr[0].y + pr[r].y * vr[1].y + pr[r].z * vr[2].y + pr[r].w * vr[3].y;
                a[r][2] += pr[r].x * vr[0].z + pr[r].y * vr[1].z + pr[r].z * vr[2].z + pr[r].w * vr[3].z;
                a[r][3] += pr[r].x * vr[0].w + pr[r].y * vr[1].w + pr[r].z * vr[2].w + pr[r].w * vr[3].w;
            }
        }
#pragma unroll
        for (int r = 0; r < 4; ++r) {
            int qi = bq + r;
            if (qi < 49) {
                int i = qi / 7, j = qi % 7;
                int sh = wy * 7 + i + 3; if (sh >= HW) sh -= HW;
                int sw = wx * 7 + j + 3; if (sw >= HW) sw -= HW;
                size_t row = (size_t)b * NTOK + sh * HW + sw;
                float4 o = make_float4(a[r][0], a[r][1], a[r][2], a[r][3]);
                *reinterpret_cast<float4*>(&out[row * CDIM + head * HDIM + bd]) = o;
            }
        }
    }
}

// ---------------- launch ----------------
extern "C" void kernel_launch(void* const* d_in, const int* in_sizes, int n_in,
                              void* d_out, int out_size) {
    const float* x     = (const float*)d_in[0];
    const float* mask  = (const float*)d_in[1];
    const float* qkv_w = (const float*)d_in[2];
    const float* qkv_b = (const float*)d_in[3];
    const float* table = (const float*)d_in[4];
    float* out = (float*)d_out;

    int nw2 = N3 * CDIM / 2;
    split_w_kernel<<<(nw2 + 255) / 256, 256>>>((const float2*)qkv_w, nw2);
    build_bias_kernel<<<(NHD * 2401 + 255) / 256, 256>>>(table);

    dim3 gg(N3 / 128, MTOT / 128);  // (6, 1568)
    qkv_gemm_kernel<<<gg, 256>>>(x, qkv_b);

    attn_kernel<<<BATCH * 1024 * NHD, 128>>>(mask, out);
}

// round 7
// speedup vs baseline: 1.6014x; 1.2493x over previous
#include <cuda_runtime.h>
#include <cuda_bf16.h>
#include <cstdint>

#define WSZ 7
#define NHD 8
#define HDIM 32
#define CDIM 256
#define HW 224
#define BATCH 4
#define NTOK (HW*HW)          // 50176
#define MTOT (BATCH*NTOK)     // 200704
#define N3 768                // 3*C
#define PAD 40                // gemm smem row stride (bf16): conflict-free for ldmatrix

// ---------------- scratch ----------------
__device__ __nv_bfloat16 g_whi[N3*CDIM];
__device__ __nv_bfloat16 g_wlo[N3*CDIM];
__device__ float g_qkv[(size_t)MTOT*N3];
__device__ float g_bias[NHD*49*49];

// ---------------- split w fp32 -> bf16 hi/lo ----------------
__global__ void split_w_kernel(const float2* __restrict__ w, int n2) {
    int i = blockIdx.x * blockDim.x + threadIdx.x;
    if (i >= n2) return;
    float2 v = w[i];
    __nv_bfloat16 h0 = __float2bfloat16(v.x);
    __nv_bfloat16 h1 = __float2bfloat16(v.y);
    __nv_bfloat16 l0 = __float2bfloat16(v.x - __bfloat162float(h0));
    __nv_bfloat16 l1 = __float2bfloat16(v.y - __bfloat162float(h1));
    reinterpret_cast<__nv_bfloat162*>(g_whi)[i] = __halves2bfloat162(h0, h1);
    reinterpret_cast<__nv_bfloat162*>(g_wlo)[i] = __halves2bfloat162(l0, l1);
}

// ---------------- relative-position bias gather ----------------
__global__ void build_bias_kernel(const float* __restrict__ table) {
    int t = blockIdx.x * blockDim.x + threadIdx.x;
    if (t >= NHD * 49 * 49) return;
    int h = t / 2401;
    int r = t % 2401;
    int q = r / 49, k = r % 49;
    int qi = q / 7, qj = q % 7, ki = k / 7, kj = k % 7;
    int rel = (qi - ki + 6) * 13 + (qj - kj + 6);
    g_bias[t] = table[rel * NHD + h];
}

// ---------------- helpers ----------------
__device__ __forceinline__ uint32_t s2u(const void* p) {
    return (uint32_t)__cvta_generic_to_shared(p);
}

#define LDSM4(R, ADDR)                                                          \
    asm volatile("ldmatrix.sync.aligned.m8n8.x4.shared.b16 {%0,%1,%2,%3}, [%4];" \
                 : "=r"((R)[0]), "=r"((R)[1]), "=r"((R)[2]), "=r"((R)[3])        \
                 : "r"(ADDR))

#define MMA16816(D, A, B0, B1)                                                   \
    asm volatile(                                                                \
        "mma.sync.aligned.m16n8k16.row.col.f32.bf16.bf16.f32 "                   \
        "{%0,%1,%2,%3}, {%4,%5,%6,%7}, {%8,%9}, {%0,%1,%2,%3};\n"                \
        : "+f"((D)[0]), "+f"((D)[1]), "+f"((D)[2]), "+f"((D)[3])                 \
        : "r"((A)[0]), "r"((A)[1]), "r"((A)[2]), "r"((A)[3]), "r"(B0), "r"(B1))

// ---------------- QKV GEMM: fused split-bf16, ldmatrix + mma ----------------
__global__ __launch_bounds__(256, 1) void qkv_gemm_kernel(
        const float* __restrict__ x, const float* __restrict__ qkv_b) {
    __shared__ __nv_bfloat16 Ahi[128 * PAD];
    __shared__ __nv_bfloat16 Alo[128 * PAD];
    __shared__ __nv_bfloat16 Bhi[128 * PAD];
    __shared__ __nv_bfloat16 Blo[128 * PAD];

    const int tid = threadIdx.x;
    const int lane = tid & 31;
    const int w = tid >> 5;
    const int wm = (w & 1) * 64;
    const int wn = (w >> 1) * 32;
    const int mbase = blockIdx.y * 128;
    const int nbase = blockIdx.x * 128;

    const int l8 = lane & 7;
    const int grp = lane >> 3;
    const int arow = l8 + (grp & 1) * 8;
    const int acol = (grp >> 1) * 8;

    const int sr = tid >> 1;
    const int sh = (tid & 1) * 16;
    const float* xbase = x + (size_t)(mbase + sr) * CDIM + sh;
    const __nv_bfloat16* whbase = g_whi + (size_t)(nbase + sr) * CDIM + sh;
    const __nv_bfloat16* wlbase = g_wlo + (size_t)(nbase + sr) * CDIM + sh;

    float acc[4][4][4];
#pragma unroll
    for (int mi = 0; mi < 4; ++mi)
#pragma unroll
        for (int nn = 0; nn < 4; ++nn)
#pragma unroll
            for (int e = 0; e < 4; ++e) acc[mi][nn][e] = 0.f;

    float4 a_st[4];
    uint4 bh_st[2], bl_st[2];

    {
        const float* ap = xbase;
        a_st[0] = *(const float4*)(ap);
        a_st[1] = *(const float4*)(ap + 4);
        a_st[2] = *(const float4*)(ap + 8);
        a_st[3] = *(const float4*)(ap + 12);
        bh_st[0] = *(const uint4*)(whbase);
        bh_st[1] = *(const uint4*)(whbase + 8);
        bl_st[0] = *(const uint4*)(wlbase);
        bl_st[1] = *(const uint4*)(wlbase + 8);
    }

    for (int kt = 0; kt < 8; ++kt) {
        {
            __align__(16) __nv_bfloat16 hi[16];
            __align__(16) __nv_bfloat16 lo[16];
#pragma unroll
            for (int i = 0; i < 4; ++i) {
                float vv[4] = {a_st[i].x, a_st[i].y, a_st[i].z, a_st[i].w};
#pragma unroll
                for (int j = 0; j < 4; ++j) {
                    __nv_bfloat16 h = __float2bfloat16(vv[j]);
                    hi[i * 4 + j] = h;
                    lo[i * 4 + j] = __float2bfloat16(vv[j] - __bfloat162float(h));
                }
            }
            *(uint4*)&Ahi[sr * PAD + sh] = *(const uint4*)&hi[0];
            *(uint4*)&Ahi[sr * PAD + sh + 8] = *(const uint4*)&hi[8];
            *(uint4*)&Alo[sr * PAD + sh] = *(const uint4*)&lo[0];
            *(uint4*)&Alo[sr * PAD + sh + 8] = *(const uint4*)&lo[8];
            *(uint4*)&Bhi[sr * PAD + sh] = bh_st[0];
            *(uint4*)&Bhi[sr * PAD + sh + 8] = bh_st[1];
            *(uint4*)&Blo[sr * PAD + sh] = bl_st[0];
            *(uint4*)&Blo[sr * PAD + sh + 8] = bl_st[1];
        }
        __syncthreads();

        if (kt < 7) {
            const float* ap = xbase + (kt + 1) * 32;
            a_st[0] = *(const float4*)(ap);
            a_st[1] = *(const float4*)(ap + 4);
            a_st[2] = *(const float4*)(ap + 8);
            a_st[3] = *(const float4*)(ap + 12);
            const __nv_bfloat16* bhp = whbase + (kt + 1) * 32;
            bh_st[0] = *(const uint4*)(bhp);
            bh_st[1] = *(const uint4*)(bhp + 8);
            const __nv_bfloat16* blp = wlbase + (kt + 1) * 32;
            bl_st[0] = *(const uint4*)(blp);
            bl_st[1] = *(const uint4*)(blp + 8);
        }

#pragma unroll
        for (int kk = 0; kk < 32; kk += 16) {
            uint32_t ah[4][4], al[4][4], bh[4][2], bl[4][2];
#pragma unroll
            for (int mi = 0; mi < 4; ++mi) {
                int off = (wm + mi * 16 + arow) * PAD + kk + acol;
                LDSM4(ah[mi], s2u(&Ahi[off]));
                LDSM4(al[mi], s2u(&Alo[off]));
            }
#pragma unroll
            for (int nj = 0; nj < 2; ++nj) {
                int off = (wn + nj * 16 + arow) * PAD + kk + acol;
                uint32_t r[4];
                LDSM4(r, s2u(&Bhi[off]));
                bh[nj * 2][0] = r[0]; bh[nj * 2][1] = r[2];
                bh[nj * 2 + 1][0] = r[1]; bh[nj * 2 + 1][1] = r[3];
                LDSM4(r, s2u(&Blo[off]));
                bl[nj * 2][0] = r[0]; bl[nj * 2][1] = r[2];
                bl[nj * 2 + 1][0] = r[1]; bl[nj * 2 + 1][1] = r[3];
            }
#pragma unroll
            for (int mi = 0; mi < 4; ++mi)
#pragma unroll
                for (int nn = 0; nn < 4; ++nn) {
                    MMA16816(acc[mi][nn], ah[mi], bh[nn][0], bh[nn][1]);
                    MMA16816(acc[mi][nn], al[mi], bh[nn][0], bh[nn][1]);
                    MMA16816(acc[mi][nn], ah[mi], bl[nn][0], bl[nn][1]);
                }
        }
        __syncthreads();
    }

    const int g = lane >> 2;
    const int tg = lane & 3;
#pragma unroll
    for (int mi = 0; mi < 4; ++mi)
#pragma unroll
        for (int nn = 0; nn < 4; ++nn) {
            int m0 = mbase + wm + mi * 16 + g;
            int n0 = nbase + wn + nn * 8 + tg * 2;
            float b0 = qkv_b[n0], b1 = qkv_b[n0 + 1];
            float2 v0 = make_float2(acc[mi][nn][0] + b0, acc[mi][nn][1] + b1);
            float2 v1 = make_float2(acc[mi][nn][2] + b0, acc[mi][nn][3] + b1);
            *reinterpret_cast<float2*>(&g_qkv[(size_t)m0 * N3 + n0]) = v0;
            *reinterpret_cast<float2*>(&g_qkv[(size_t)(m0 + 8) * N3 + n0]) = v1;
        }
}

// ---------------- windowed attention: broadcast-friendly warp layout ----------------
// CTA = (window, head), 224 threads = 7 warps.
// QK^T: warp w owns q rows [8w, 8w+8) (q loads broadcast), lane owns k columns
//       {lane, lane+32} via transposed K (stride-1 LDS.32).
// PV:   warp w owns q rows, lane owns d = lane (stride-1 vs loads, P broadcast).
__global__ __launch_bounds__(224) void attn_kernel(const float* __restrict__ mask,
                                                   float* __restrict__ out) {
    __shared__ float qs[56][36];    // q rows, zero-padded rows 49..55
    __shared__ float ksT[32][68];   // K transposed: ksT[d][k], cols 49..63 zero
    __shared__ float vs[52][36];    // V rows, zero-padded rows 49..51
    __shared__ float S[56][68];     // logits -> probabilities

    const int tid = threadIdx.x;
    const int lane = tid & 31;
    const int w = tid >> 5;         // 0..6
    const int bid = blockIdx.x;
    const int head = bid & 7;
    const int win = bid >> 3;
    const int b = win >> 10;
    const int widx = win & 1023;
    const int wy = widx >> 5, wx = widx & 31;

    // ---- gather (shift folded into source coords) ----
    for (int idx = tid; idx < 512; idx += 224) {
        int p = idx >> 3, d4 = (idx & 7) << 2;
        float4 q4 = make_float4(0.f, 0.f, 0.f, 0.f);
        float4 k4 = q4, v4 = q4;
        if (p < 49) {
            int i = p / 7, j = p % 7;
            int sh = wy * 7 + i + 3; if (sh >= HW) sh -= HW;
            int sw = wx * 7 + j + 3; if (sw >= HW) sw -= HW;
            size_t row = (size_t)b * NTOK + sh * HW + sw;
            const float* base = g_qkv + row * N3 + head * HDIM + d4;
            q4 = *(const float4*)(base);
            k4 = *(const float4*)(base + 256);
            v4 = *(const float4*)(base + 512);
        }
        if (p < 56) *(float4*)&qs[p][d4] = q4;
        if (p < 52) *(float4*)&vs[p][d4] = v4;
        ksT[d4 + 0][p] = k4.x;
        ksT[d4 + 1][p] = k4.y;
        ksT[d4 + 2][p] = k4.z;
        ksT[d4 + 3][p] = k4.w;
    }
    __syncthreads();

    const float scale = 0.17677669529663687f;  // 32^-0.5
    const int qb = w * 8;

    // ---- S = QK^T ----
    {
        float acc[8][2];
#pragma unroll
        for (int r = 0; r < 8; ++r) { acc[r][0] = 0.f; acc[r][1] = 0.f; }

#pragma unroll
        for (int d = 0; d < 32; d += 4) {
            float k0[4], k1[4];
#pragma unroll
            for (int j = 0; j < 4; ++j) {
                k0[j] = ksT[d + j][lane];
                k1[j] = ksT[d + j][lane + 32];
            }
#pragma unroll
            for (int r = 0; r < 8; ++r) {
                float4 q4 = *(const float4*)&qs[qb + r][d];   // broadcast
                acc[r][0] += q4.x * k0[0] + q4.y * k0[1] + q4.z * k0[2] + q4.w * k0[3];
                acc[r][1] += q4.x * k1[0] + q4.y * k1[1] + q4.z * k1[2] + q4.w * k1[3];
            }
        }

        const int k1i = lane + 32;
#pragma unroll
        for (int r = 0; r < 8; ++r) {
            int qi = qb + r;
            if (qi < 49) {
                int bb = head * 2401 + qi * 49;
                size_t mm = (size_t)widx * 2401 + qi * 49;
                S[qi][lane] = acc[r][0] * scale + g_bias[bb + lane] + mask[mm + lane];
                if (k1i < 49)
                    S[qi][k1i] = acc[r][1] * scale + g_bias[bb + k1i] + mask[mm + k1i];
            }
        }
    }
    __syncthreads();

    // ---- softmax: warp-collective per row (lane-per-column + shuffle reduce) ----
    for (int row = w; row < 49; row += 7) {
        float v0 = S[row][lane];
        float v1 = (lane + 32 < 49) ? S[row][lane + 32] : -1e30f;
        float m = fmaxf(v0, v1);
#pragma unroll
        for (int off = 16; off; off >>= 1) m = fmaxf(m, __shfl_xor_sync(0xffffffffu, m, off));
        float e0 = __expf(v0 - m);
        float e1 = (lane + 32 < 49) ? __expf(v1 - m) : 0.f;
        float s = e0 + e1;
#pragma unroll
        for (int off = 16; off; off >>= 1) s += __shfl_xor_sync(0xffffffffu, s, off);
        float inv = 1.f / s;
        S[row][lane] = e0 * inv;
        S[row][lane + 32] = e1 * inv;   // zeros for cols 49..63
    }
    __syncthreads();

    // ---- O = P @ V : lane = d, warp = q block ----
    {
        float oacc[8];
#pragma unroll
        for (int r = 0; r < 8; ++r) oacc[r] = 0.f;

        for (int k = 0; k < 52; k += 4) {
            float vv[4];
#pragma unroll
            for (int j = 0; j < 4; ++j) vv[j] = vs[k + j][lane];   // stride-1
#pragma unroll
            for (int r = 0; r < 8; ++r) {
                if (qb + r < 49) {
                    float4 p4 = *(const float4*)&S[qb + r][k];     // broadcast
                    oacc[r] += p4.x * vv[0] + p4.y * vv[1] + p4.z * vv[2] + p4.w * vv[3];
                }
            }
        }

#pragma unroll
        for (int r = 0; r < 8; ++r) {
            int qi = qb + r;
            if (qi < 49) {
                int i = qi / 7, j = qi % 7;
                int sh = wy * 7 + i + 3; if (sh >= HW) sh -= HW;
                int sw = wx * 7 + j + 3; if (sw >= HW) sw -= HW;
                size_t row = (size_t)b * NTOK + sh * HW + sw;
                out[row * CDIM + head * HDIM + lane] = oacc[r];
            }
        }
    }
}

// ---------------- launch ----------------
extern "C" void kernel_launch(void* const* d_in, const int* in_sizes, int n_in,
                              void* d_out, int out_size) {
    const float* x     = (const float*)d_in[0];
    const float* mask  = (const float*)d_in[1];
    const float* qkv_w = (const float*)d_in[2];
    const float* qkv_b = (const float*)d_in[3];
    const float* table = (const float*)d_in[4];
    float* out = (float*)d_out;

    int nw2 = N3 * CDIM / 2;
    split_w_kernel<<<(nw2 + 255) / 256, 256>>>((const float2*)qkv_w, nw2);
    build_bias_kernel<<<(NHD * 2401 + 255) / 256, 256>>>(table);

    dim3 gg(N3 / 128, MTOT / 128);  // (6, 1568)
    qkv_gemm_kernel<<<gg, 256>>>(x, qkv_b);

    attn_kernel<<<BATCH * 1024 * NHD, 224>>>(mask, out);
}

// round 9
// speedup vs baseline: 2.1120x; 1.3188x over previous
#include <cuda_runtime.h>
#include <cuda_fp16.h>
#include <cstdint>

#define WSZ 7
#define NHD 8
#define HDIM 32
#define CDIM 256
#define HW 224
#define BATCH 4
#define NTOK (HW*HW)          // 50176
#define MTOT (BATCH*NTOK)     // 200704
#define N3 768                // 3*C
#define PAD 40                // gemm smem row stride (fp16): conflict-free for ldmatrix

// ---------------- scratch ----------------
__device__ __half g_wh[N3*CDIM];
__device__ float g_qkv[(size_t)MTOT*N3];
__device__ float g_bias[NHD*49*49];
__device__ int   g_src[1024*49];

// ---------------- w fp32 -> fp16 ----------------
__global__ void conv_w_kernel(const float2* __restrict__ w, int n2) {
    int i = blockIdx.x * blockDim.x + threadIdx.x;
    if (i >= n2) return;
    float2 v = w[i];
    reinterpret_cast<__half2*>(g_wh)[i] = __floats2half2_rn(v.x, v.y);
}

// ---------------- relative-position bias gather ----------------
__global__ void build_bias_kernel(const float* __restrict__ table) {
    int t = blockIdx.x * blockDim.x + threadIdx.x;
    if (t >= NHD * 49 * 49) return;
    int h = t / 2401;
    int r = t % 2401;
    int q = r / 49, k = r % 49;
    int qi = q / 7, qj = q % 7, ki = k / 7, kj = k % 7;
    int rel = (qi - ki + 6) * 13 + (qj - kj + 6);
    g_bias[t] = table[rel * NHD + h];
}

// ---------------- gather-row table: (widx, p) -> spatial row in batch plane ----
__global__ void build_src_kernel() {
    int t = blockIdx.x * blockDim.x + threadIdx.x;
    if (t >= 1024 * 49) return;
    int widx = t / 49, p = t % 49;
    int wy = widx >> 5, wx = widx & 31;
    int i = p / 7, j = p % 7;
    int sh = wy * 7 + i + 3; if (sh >= HW) sh -= HW;
    int sw = wx * 7 + j + 3; if (sw >= HW) sw -= HW;
    g_src[t] = sh * HW + sw;
}

// ---------------- helpers ----------------
__device__ __forceinline__ uint32_t s2u(const void* p) {
    return (uint32_t)__cvta_generic_to_shared(p);
}

#define LDSM4(R, ADDR)                                                          \
    asm volatile("ldmatrix.sync.aligned.m8n8.x4.shared.b16 {%0,%1,%2,%3}, [%4];" \
                 : "=r"((R)[0]), "=r"((R)[1]), "=r"((R)[2]), "=r"((R)[3])        \
                 : "r"(ADDR))

#define MMA16816F(D, A, B0, B1)                                                  \
    asm volatile(                                                                \
        "mma.sync.aligned.m16n8k16.row.col.f32.f16.f16.f32 "                     \
        "{%0,%1,%2,%3}, {%4,%5,%6,%7}, {%8,%9}, {%0,%1,%2,%3};\n"                \
        : "+f"((D)[0]), "+f"((D)[1]), "+f"((D)[2]), "+f"((D)[3])                 \
        : "r"((A)[0]), "r"((A)[1]), "r"((A)[2]), "r"((A)[3]), "r"(B0), "r"(B1))

// ---------------- QKV GEMM: 2-term fp16 split, ldmatrix + mma ----------------
// out[m,n] = sum_k x[m,k] w[n,k] + b[n]
// x split on the fly: x = xhi + xlo (fp16 pair); w single fp16.
// acc += xhi*wh + xlo*wh   (dropped term x*(w - wh): ~2.8e-4 rms relative)
// CTA 128(M) x 128(N), k-tile 32, 256 thr = 8 warps, warp tile 64x32, 2 CTA/SM.
__global__ __launch_bounds__(256, 2) void qkv_gemm_kernel(
        const float* __restrict__ x, const float* __restrict__ qkv_b) {
    __shared__ __half Ahi[128 * PAD];
    __shared__ __half Alo[128 * PAD];
    __shared__ __half Bh[128 * PAD];

    const int tid = threadIdx.x;
    const int lane = tid & 31;
    const int w = tid >> 5;
    const int wm = (w & 1) * 64;
    const int wn = (w >> 1) * 32;
    const int mbase = blockIdx.y * 128;
    const int nbase = blockIdx.x * 128;

    const int l8 = lane & 7;
    const int grp = lane >> 3;
    const int arow = l8 + (grp & 1) * 8;
    const int acol = (grp >> 1) * 8;

    const int sr = tid >> 1;
    const int sh = (tid & 1) * 16;
    const float* xbase = x + (size_t)(mbase + sr) * CDIM + sh;
    const __half* wbase = g_wh + (size_t)(nbase + sr) * CDIM + sh;

    float acc[4][4][4];
#pragma unroll
    for (int mi = 0; mi < 4; ++mi)
#pragma unroll
        for (int nn = 0; nn < 4; ++nn)
#pragma unroll
            for (int e = 0; e < 4; ++e) acc[mi][nn][e] = 0.f;

    float4 a_st[4];
    uint4 b_st[2];

    {
        const float* ap = xbase;
        a_st[0] = *(const float4*)(ap);
        a_st[1] = *(const float4*)(ap + 4);
        a_st[2] = *(const float4*)(ap + 8);
        a_st[3] = *(const float4*)(ap + 12);
        b_st[0] = *(const uint4*)(wbase);
        b_st[1] = *(const uint4*)(wbase + 8);
    }

    for (int kt = 0; kt < 8; ++kt) {
        {
            __align__(16) __half hi[16];
            __align__(16) __half lo[16];
#pragma unroll
            for (int i = 0; i < 4; ++i) {
                float vv[4] = {a_st[i].x, a_st[i].y, a_st[i].z, a_st[i].w};
#pragma unroll
                for (int j = 0; j < 4; ++j) {
                    __half h = __float2half_rn(vv[j]);
                    hi[i * 4 + j] = h;
                    lo[i * 4 + j] = __float2half_rn(vv[j] - __half2float(h));
                }
            }
            *(uint4*)&Ahi[sr * PAD + sh] = *(const uint4*)&hi[0];
            *(uint4*)&Ahi[sr * PAD + sh + 8] = *(const uint4*)&hi[8];
            *(uint4*)&Alo[sr * PAD + sh] = *(const uint4*)&lo[0];
            *(uint4*)&Alo[sr * PAD + sh + 8] = *(const uint4*)&lo[8];
            *(uint4*)&Bh[sr * PAD + sh] = b_st[0];
            *(uint4*)&Bh[sr * PAD + sh + 8] = b_st[1];
        }
        __syncthreads();

        if (kt < 7) {
            const float* ap = xbase + (kt + 1) * 32;
            a_st[0] = *(const float4*)(ap);
            a_st[1] = *(const float4*)(ap + 4);
            a_st[2] = *(const float4*)(ap + 8);
            a_st[3] = *(const float4*)(ap + 12);
            const __half* bp = wbase + (kt + 1) * 32;
            b_st[0] = *(const uint4*)(bp);
            b_st[1] = *(const uint4*)(bp + 8);
        }

#pragma unroll
        for (int kk = 0; kk < 32; kk += 16) {
            uint32_t ah[4][4], al[4][4], bh[4][2];
#pragma unroll
            for (int mi = 0; mi < 4; ++mi) {
                int off = (wm + mi * 16 + arow) * PAD + kk + acol;
                LDSM4(ah[mi], s2u(&Ahi[off]));
                LDSM4(al[mi], s2u(&Alo[off]));
            }
#pragma unroll
            for (int nj = 0; nj < 2; ++nj) {
                int off = (wn + nj * 16 + arow) * PAD + kk + acol;
                uint32_t r[4];
                LDSM4(r, s2u(&Bh[off]));
                bh[nj * 2][0] = r[0]; bh[nj * 2][1] = r[2];
                bh[nj * 2 + 1][0] = r[1]; bh[nj * 2 + 1][1] = r[3];
            }
#pragma unroll
            for (int mi = 0; mi < 4; ++mi)
#pragma unroll
                for (int nn = 0; nn < 4; ++nn) {
                    MMA16816F(acc[mi][nn], ah[mi], bh[nn][0], bh[nn][1]);
                    MMA16816F(acc[mi][nn], al[mi], bh[nn][0], bh[nn][1]);
                }
        }
        __syncthreads();
    }

    const int g = lane >> 2;
    const int tg = lane & 3;
#pragma unroll
    for (int mi = 0; mi < 4; ++mi)
#pragma unroll
        for (int nn = 0; nn < 4; ++nn) {
            int m0 = mbase + wm + mi * 16 + g;
            int n0 = nbase + wn + nn * 8 + tg * 2;
            float b0 = qkv_b[n0], b1 = qkv_b[n0 + 1];
            float2 v0 = make_float2(acc[mi][nn][0] + b0, acc[mi][nn][1] + b1);
            float2 v1 = make_float2(acc[mi][nn][2] + b0, acc[mi][nn][3] + b1);
            *reinterpret_cast<float2*>(&g_qkv[(size_t)m0 * N3 + n0]) = v0;
            *reinterpret_cast<float2*>(&g_qkv[(size_t)(m0 + 8) * N3 + n0]) = v1;
        }
}

// ---------------- windowed attention (R7 layout + index table) ----------------
__global__ __launch_bounds__(224) void attn_kernel(const float* __restrict__ mask,
                                                   float* __restrict__ out) {
    __shared__ float qs[56][36];
    __shared__ float ksT[32][68];
    __shared__ float vs[52][36];
    __shared__ float S[56][68];

    const int tid = threadIdx.x;
    const int lane = tid & 31;
    const int w = tid >> 5;
    const int bid = blockIdx.x;
    const int head = bid & 7;
    const int win = bid >> 3;
    const int b = win >> 10;
    const int widx = win & 1023;
    const int* srcp = g_src + widx * 49;
    const size_t brow = (size_t)b * NTOK;

    for (int idx = tid; idx < 512; idx += 224) {
        int p = idx >> 3, d4 = (idx & 7) << 2;
        float4 q4 = make_float4(0.f, 0.f, 0.f, 0.f);
        float4 k4 = q4, v4 = q4;
        if (p < 49) {
            size_t row = brow + srcp[p];
            const float* base = g_qkv + row * N3 + head * HDIM + d4;
            q4 = *(const float4*)(base);
            k4 = *(const float4*)(base + 256);
            v4 = *(const float4*)(base + 512);
        }
        if (p < 56) *(float4*)&qs[p][d4] = q4;
        if (p < 52) *(float4*)&vs[p][d4] = v4;
        ksT[d4 + 0][p] = k4.x;
        ksT[d4 + 1][p] = k4.y;
        ksT[d4 + 2][p] = k4.z;
        ksT[d4 + 3][p] = k4.w;
    }
    __syncthreads();

    const float scale = 0.17677669529663687f;  // 32^-0.5
    const int qb = w * 8;

    {
        float acc[8][2];
#pragma unroll
        for (int r = 0; r < 8; ++r) { acc[r][0] = 0.f; acc[r][1] = 0.f; }

#pragma unroll
        for (int d = 0; d < 32; d += 4) {
            float k0[4], k1[4];
#pragma unroll
            for (int j = 0; j < 4; ++j) {
                k0[j] = ksT[d + j][lane];
                k1[j] = ksT[d + j][lane + 32];
            }
#pragma unroll
            for (int r = 0; r < 8; ++r) {
                float4 q4 = *(const float4*)&qs[qb + r][d];
                acc[r][0] += q4.x * k0[0] + q4.y * k0[1] + q4.z * k0[2] + q4.w * k0[3];
                acc[r][1] += q4.x * k1[0] + q4.y * k1[1] + q4.z * k1[2] + q4.w * k1[3];
            }
        }

        const int k1i = lane + 32;
#pragma unroll
        for (int r = 0; r < 8; ++r) {
            int qi = qb + r;
            if (qi < 49) {
                int bb = head * 2401 + qi * 49;
                size_t mm = (size_t)widx * 2401 + qi * 49;
                S[qi][lane] = acc[r][0] * scale + g_bias[bb + lane] + mask[mm + lane];
                if (k1i < 49)
                    S[qi][k1i] = acc[r][1] * scale + g_bias[bb + k1i] + mask[mm + k1i];
            }
        }
    }
    __syncthreads();

    for (int row = w; row < 49; row += 7) {
        float v0 = S[row][lane];
        float v1 = (lane + 32 < 49) ? S[row][lane + 32] : -1e30f;
        float m = fmaxf(v0, v1);
#pragma unroll
        for (int off = 16; off; off >>= 1) m = fmaxf(m, __shfl_xor_sync(0xffffffffu, m, off));
        float e0 = __expf(v0 - m);
        float e1 = (lane + 32 < 49) ? __expf(v1 - m) : 0.f;
        float s = e0 + e1;
#pragma unroll
        for (int off = 16; off; off >>= 1) s += __shfl_xor_sync(0xffffffffu, s, off);
        float inv = 1.f / s;
        S[row][lane] = e0 * inv;
        S[row][lane + 32] = e1 * inv;
    }
    __syncthreads();

    {
        float oacc[8];
#pragma unroll
        for (int r = 0; r < 8; ++r) oacc[r] = 0.f;

        for (int k = 0; k < 52; k += 4) {
            float vv[4];
#pragma unroll
            for (int j = 0; j < 4; ++j) vv[j] = vs[k + j][lane];
#pragma unroll
            for (int r = 0; r < 8; ++r) {
                if (qb + r < 49) {
                    float4 p4 = *(const float4*)&S[qb + r][k];
                    oacc[r] += p4.x * vv[0] + p4.y * vv[1] + p4.z * vv[2] + p4.w * vv[3];
                }
            }
        }

#pragma unroll
        for (int r = 0; r < 8; ++r) {
            int qi = qb + r;
            if (qi < 49) {
                size_t row = brow + srcp[qi];
                out[row * CDIM + head * HDIM + lane] = oacc[r];
            }
        }
    }
}

// ---------------- launch ----------------
extern "C" void kernel_launch(void* const* d_in, const int* in_sizes, int n_in,
                              void* d_out, int out_size) {
    const float* x     = (const float*)d_in[0];
    const float* mask  = (const float*)d_in[1];
    const float* qkv_w = (const float*)d_in[2];
    const float* qkv_b = (const float*)d_in[3];
    const float* table = (const float*)d_in[4];
    float* out = (float*)d_out;

    int nw2 = N3 * CDIM / 2;
    conv_w_kernel<<<(nw2 + 255) / 256, 256>>>((const float2*)qkv_w, nw2);
    build_bias_kernel<<<(NHD * 2401 + 255) / 256, 256>>>(table);
    build_src_kernel<<<(1024 * 49 + 255) / 256, 256>>>();

    dim3 gg(N3 / 128, MTOT / 128);  // (6, 1568)
    qkv_gemm_kernel<<<gg, 256>>>(x, qkv_b);

    attn_kernel<<<BATCH * 1024 * NHD, 224>>>(mask, out);
}